// round 12
// baseline (speedup 1.0000x reference)
#include <cuda_runtime.h>
#include <cuda_bf16.h>
#include <math_constants.h>
#include <cstdint>

#define BB    64
#define TT    2048
#define DRNN  1024
#define DEMB  512
#define DATT  128
#define NF    32
#define KS    31
#define PADW  15
#define NSPLIT 16

#define KPAD   104
#define ROWB   208

// ---- energy kernel dynamic smem layout (bytes) ----
#define SM_B     0                         // Wd image: 128 x 208 B
#define SM_LOCB  26624                     // loc bf16: 128 x 208 B
#define SM_AW    53248                     // 2*160 floats
#define SM_CW    54528                     // 62*32 floats
#define SM_PQ    62464                     // 128 floats
#define SM_WV    62976                     // 128 floats
#define SM_E     63488                     // 128 floats
#define SM_PM    64000                     // pm stage: 8 warps x 16 rows x 272 B
#define PM_ROWB  272                       // 68 floats (16B-aligned, bank-skewed)
#define PM_WARPB (16 * PM_ROWB)            // 4352
#define SM_TOTAL (SM_PM + 8 * PM_WARPB)    // 98816

// ---------------- device scratch ----------------
__device__ float  g_pq[BB * DATT];
__device__ float2 g_cw2[62 * 16];
__device__ unsigned short g_wdbp[128 * KPAD];  // B image [a][k] bf16: Wh|Wh|Wl|0pad
__device__ float  g_energy[BB * TT];
__device__ float  g_ctx_part[NSPLIT * BB * DEMB];

typedef unsigned long long ull;

// ---------------- helpers ----------------
__device__ __forceinline__ ull ffma2u(ull a, ull b, ull c) {
    ull d;
    asm("fma.rn.f32x2 %0, %1, %2, %3;" : "=l"(d) : "l"(a), "l"(b), "l"(c));
    return d;
}
__device__ __forceinline__ ull pack2(float x, float y) {
    ull r; asm("mov.b64 %0, {%1, %2};" : "=l"(r) : "f"(x), "f"(y)); return r;
}
__device__ __forceinline__ float2 unpack2(ull v) {
    float2 f; asm("mov.b64 {%0, %1}, %2;" : "=f"(f.x), "=f"(f.y) : "l"(v)); return f;
}
__device__ __forceinline__ float tanh_fast(float x) {
    float y; asm("tanh.approx.f32 %0, %1;" : "=f"(y) : "f"(x)); return y;
}
__device__ __forceinline__ uint32_t smem_u32(const void* p) {
    uint32_t a;
    asm("{ .reg .u64 t; cvta.to.shared.u64 t, %1; cvt.u32.u64 %0, t; }" : "=r"(a) : "l"(p));
    return a;
}
__device__ __forceinline__ void cp_async16(uint32_t dst, const void* src) {
    asm volatile("cp.async.ca.shared.global [%0], [%1], 16;" :: "r"(dst), "l"(src));
}
__device__ __forceinline__ void ldsm4(uint32_t* r, uint32_t addr) {
    asm volatile("ldmatrix.sync.aligned.m8n8.x4.shared.b16 {%0,%1,%2,%3}, [%4];"
        : "=r"(r[0]), "=r"(r[1]), "=r"(r[2]), "=r"(r[3]) : "r"(addr));
}
__device__ __forceinline__ void mma_bf16(float* d, const uint32_t* a,
                                         uint32_t b0, uint32_t b1) {
    asm volatile("mma.sync.aligned.m16n8k16.row.col.f32.bf16.bf16.f32 "
        "{%0,%1,%2,%3}, {%4,%5,%6,%7}, {%8,%9}, {%0,%1,%2,%3};"
        : "+f"(d[0]), "+f"(d[1]), "+f"(d[2]), "+f"(d[3])
        : "r"(a[0]), "r"(a[1]), "r"(a[2]), "r"(a[3]), "r"(b0), "r"(b1));
}

// ---------------- K0: pq GEMM (16x parallel) + conv repack + Wd bf16 image ----------------
__global__ __launch_bounds__(128) void prep_kernel(
    const float* __restrict__ hidden, const float* __restrict__ Wq,
    const float* __restrict__ convw,  const float* __restrict__ Wd)
{
    __shared__ float s_h[DRNN];
    int tid = threadIdx.x, b = blockIdx.x, slice = blockIdx.y;
    for (int i = tid; i < DRNN; i += 128) s_h[i] = hidden[(size_t)b * DRNN + i];
    __syncthreads();

    int w = tid >> 5, lane = tid & 31;
    int a0 = slice * 8 + w * 2;
    const float* wq0 = Wq + (size_t)a0 * DRNN;
    const float* wq1 = wq0 + DRNN;
    float a00 = 0.f, a01 = 0.f, a10 = 0.f, a11 = 0.f;
    #pragma unroll 4
    for (int k = lane; k < DRNN; k += 64) {
        float h0 = s_h[k], h1 = s_h[k + 32];
        a00 = fmaf(h0, wq0[k],      a00);
        a01 = fmaf(h1, wq0[k + 32], a01);
        a10 = fmaf(h0, wq1[k],      a10);
        a11 = fmaf(h1, wq1[k + 32], a11);
    }
    float rA = a00 + a01, rB = a10 + a11;
    #pragma unroll
    for (int off = 16; off; off >>= 1) {
        rA += __shfl_down_sync(0xffffffffu, rA, off);
        rB += __shfl_down_sync(0xffffffffu, rB, off);
    }
    if (lane == 0) {
        g_pq[b * DATT + a0]     = rA;
        g_pq[b * DATT + a0 + 1] = rB;
    }

    if (b == 0 && slice == 0) {
        for (int i = tid; i < 62 * 16; i += 128) {
            int ck = i >> 4, fp = i & 15;
            g_cw2[i] = make_float2(convw[(2 * fp) * 62 + ck], convw[(2 * fp + 1) * 62 + ck]);
        }
    }
    if (b == 1 && slice == 0) {
        int a = tid;
        if (a < 128) {
            const float* wrow = Wd + a * NF;
            unsigned short* orow = g_wdbp + a * KPAD;
            #pragma unroll 4
            for (int k = 0; k < KPAD; k++) {
                __nv_bfloat16 bv = __float2bfloat16(0.f);
                if (k < 64) {
                    bv = __float2bfloat16(wrow[k & 31]);
                } else if (k < 96) {
                    float orig = wrow[k - 64];
                    float hi = __bfloat162float(__float2bfloat16(orig));
                    bv = __float2bfloat16(orig - hi);
                }
                orow[k] = *(unsigned short*)&bv;
            }
        }
    }
}

__global__ void dummy_kernel() {}

// ---------------- K1: conv + mma.sync paw + tanh + v-dot -> energies ----------------
// 256 threads = 8 warps. Warp w owns m16 tile rows mb=16w..mb+15, all 128 a.
// pm staged per-warp per-nh-half through smem via cp.async (coalesced); the
// nh=0 copy is issued at kernel start so the conv phase hides its latency.
__global__ __launch_bounds__(256) void energy_kernel(
    const float* __restrict__ pm, const float* __restrict__ aw,
    const float* __restrict__ wv)
{
    extern __shared__ __align__(16) char smc[];
    float* s_aw = (float*)(smc + SM_AW);
    float* s_cw = (float*)(smc + SM_CW);
    float* s_pq = (float*)(smc + SM_PQ);
    float* s_wv = (float*)(smc + SM_WV);
    float* s_e  = (float*)(smc + SM_E);

    int tid = threadIdx.x;
    int b   = blockIdx.y;
    int t0  = blockIdx.x * 128;
    int w   = tid >> 5, lane = tid & 31;
    const int mb = w * 16;
    uint32_t sbase = smem_u32(smc);

    // ---- pm phase-0 cp.async (issued first; conv hides the latency) ----
    const uint32_t pmS = sbase + SM_PM + w * PM_WARPB;
    const char* pmG = (const char*)(pm + ((size_t)b * TT + t0 + mb) * DATT);
    // lane copies 8 x 16B chunks per phase: chunk c -> row c>>4, seg c&15
    #define PM_ISSUE(nh) do {                                                  \
        _Pragma("unroll")                                                      \
        for (int j_ = 0; j_ < 8; j_++) {                                       \
            int c_ = lane + j_ * 32;                                           \
            int row_ = c_ >> 4, seg_ = c_ & 15;                                \
            cp_async16(pmS + row_ * PM_ROWB + seg_ * 16,                       \
                       pmG + row_ * 512 + (nh) * 256 + seg_ * 16);             \
        }                                                                      \
        asm volatile("cp.async.commit_group;" ::: "memory");                   \
    } while (0)
    PM_ISSUE(0);

    // ---- stage: B image, conv inputs, pq, wv ----
    {
        const float4* src = (const float4*)g_wdbp;     // 1664 float4
        float4* dst = (float4*)(smc + SM_B);
        for (int i = tid; i < 1664; i += 256) dst[i] = src[i];
    }
    const float* awB = aw + (size_t)b * 2 * TT;
    for (int i = tid; i < 2 * 158; i += 256) {
        int c = i / 158, j = i - c * 158;
        int tg = t0 + j - PADW;
        s_aw[c * 160 + j] = (tg >= 0 && tg < TT) ? awB[(size_t)c * TT + tg] : 0.f;
    }
    {
        const float4* src = (const float4*)g_cw2;      // 496 float4
        float4* dst = (float4*)s_cw;
        for (int i = tid; i < 496; i += 256) dst[i] = src[i];
    }
    if (tid < 128) {
        s_pq[tid] = g_pq[b * DATT + tid];
        s_wv[tid] = wv[tid];
    }
    __syncthreads();

    // ---- conv: thread (tloc = tid&127, fh = tid>>7) -> loc[t][16 filters] ----
    {
        const int tloc = tid & 127, fh = tid >> 7;
        ull cacc[8];
        #pragma unroll
        for (int i = 0; i < 8; i++) cacc[i] = 0ULL;
        #pragma unroll 2
        for (int ck = 0; ck < 62; ck++) {
            int c = (ck >= 31), k = ck - c * 31;
            float av = s_aw[c * 160 + tloc + k];
            ull av2 = pack2(av, av);
            const ulonglong2* row = (const ulonglong2*)(s_cw + ck * 32 + fh * 16);
            #pragma unroll
            for (int q = 0; q < 4; q++) {
                ulonglong2 w2 = row[q];
                cacc[2 * q]     = ffma2u(av2, w2.x, cacc[2 * q]);
                cacc[2 * q + 1] = ffma2u(av2, w2.y, cacc[2 * q + 1]);
            }
        }
        uint32_t awords[24];
        #pragma unroll
        for (int fp = 0; fp < 8; fp++) {
            float2 v = unpack2(cacc[fp]);
            __nv_bfloat16 h0 = __float2bfloat16(v.x), h1 = __float2bfloat16(v.y);
            float r0 = v.x - __bfloat162float(h0);
            float r1 = v.y - __bfloat162float(h1);
            __nv_bfloat16 l0 = __float2bfloat16(r0), l1 = __float2bfloat16(r1);
            uint32_t hw = ((uint32_t)__bfloat16_as_ushort(h1) << 16) | __bfloat16_as_ushort(h0);
            uint32_t lw = ((uint32_t)__bfloat16_as_ushort(l1) << 16) | __bfloat16_as_ushort(l0);
            awords[fp]      = hw;
            awords[8 + fp]  = lw;
            awords[16 + fp] = hw;
        }
        char* base = smc + SM_LOCB + tloc * ROWB + fh * 32;
        #pragma unroll
        for (int sgm = 0; sgm < 3; sgm++) {
            uint4* dst = (uint4*)(base + sgm * 64);
            dst[0] = make_uint4(awords[8 * sgm],     awords[8 * sgm + 1],
                                awords[8 * sgm + 2], awords[8 * sgm + 3]);
            dst[1] = make_uint4(awords[8 * sgm + 4], awords[8 * sgm + 5],
                                awords[8 * sgm + 6], awords[8 * sgm + 7]);
        }
    }
    __syncthreads();

    // ---- per-warp MMA + epilogue ----
    const uint32_t sLocb = sbase + SM_LOCB;
    const uint32_t sBimg = sbase + SM_B;
    const int lr = lane >> 2;                 // local row within m16 tile
    const int r0 = mb + lr;
    const int ac = 2 * (lane & 3);

    // A fragments hoisted: loaded once, used for both n-halves
    uint32_t af[6][4];
    #pragma unroll
    for (int ks = 0; ks < 6; ks++)
        ldsm4(af[ks], sLocb + (mb + (lane & 15)) * ROWB + (ks * 16 + (lane >> 4) * 8) * 2);

    float es0 = 0.f, es1 = 0.f;
    const float* pmw0 = (const float*)(smc + SM_PM + w * PM_WARPB + lr * PM_ROWB);
    const float* pmw1 = (const float*)(smc + SM_PM + w * PM_WARPB + (lr + 8) * PM_ROWB);

    #pragma unroll
    for (int nh = 0; nh < 2; nh++) {
        asm volatile("cp.async.wait_group 0;" ::: "memory");
        __syncwarp();

        float acc[8][4];
        #pragma unroll
        for (int nt = 0; nt < 8; nt++)
            #pragma unroll
            for (int q = 0; q < 4; q++) acc[nt][q] = 0.f;

        #pragma unroll
        for (int ks = 0; ks < 6; ks++) {
            const int kk = ks * 16;
            uint32_t bf[4][4];
            #pragma unroll
            for (int ng = 0; ng < 4; ng++) {
                uint32_t baddr = sBimg
                    + (nh * 64 + ng * 16 + ((lane >> 4) << 3) + (lane & 7)) * ROWB
                    + (kk + ((lane >> 3) & 1) * 8) * 2;
                ldsm4(bf[ng], baddr);
            }
            #pragma unroll
            for (int ng = 0; ng < 4; ng++) {
                mma_bf16(acc[2 * ng],     af[ks], bf[ng][0], bf[ng][1]);
                mma_bf16(acc[2 * ng + 1], af[ks], bf[ng][2], bf[ng][3]);
            }
        }

        // epilogue: pm from staged smem (conflict-free quad pattern)
        #pragma unroll
        for (int nt = 0; nt < 8; nt++) {
            int cl = nt * 8 + ac;             // local col within nh-half
            int a0 = nh * 64 + cl;
            float2 p0 = *(const float2*)(pmw0 + cl);
            float2 p1 = *(const float2*)(pmw1 + cl);
            float2 q  = *(const float2*)(s_pq + a0);
            float2 v  = *(const float2*)(s_wv + a0);
            const float* c = acc[nt];
            es0 = fmaf(v.x, tanh_fast(c[0] + q.x + p0.x), es0);
            es0 = fmaf(v.y, tanh_fast(c[1] + q.y + p0.y), es0);
            es1 = fmaf(v.x, tanh_fast(c[2] + q.x + p1.x), es1);
            es1 = fmaf(v.y, tanh_fast(c[3] + q.y + p1.y), es1);
        }

        if (nh == 0) {
            __syncwarp();                     // all lanes done reading phase 0
            PM_ISSUE(1);
        }
    }

    // quad reduction (lanes l^1, l^2)
    #pragma unroll
    for (int off = 1; off <= 2; off <<= 1) {
        es0 += __shfl_xor_sync(0xffffffffu, es0, off);
        es1 += __shfl_xor_sync(0xffffffffu, es1, off);
    }
    if ((lane & 3) == 0) {
        s_e[r0]     = es0;
        s_e[r0 + 8] = es1;
    }
    __syncthreads();
    if (tid < 128) g_energy[(size_t)b * TT + t0 + tid] = s_e[tid];
}

// ---------------- K2: masked softmax (mask = int32) ----------------
__global__ __launch_bounds__(256) void softmax_kernel(
    const int* __restrict__ mask, float* __restrict__ out_w)
{
    __shared__ float red[32];
    int tid = threadIdx.x, b = blockIdx.x;
    float vals[8];
    float mx = -CUDART_INF_F;
    #pragma unroll
    for (int j = 0; j < 8; j++) {
        int t = tid + j * 256;
        float e = g_energy[(size_t)b * TT + t];
        float v = (mask[(size_t)b * TT + t] != 0) ? -CUDART_INF_F : e;
        vals[j] = v;
        mx = fmaxf(mx, v);
    }
    #pragma unroll
    for (int off = 16; off; off >>= 1) mx = fmaxf(mx, __shfl_xor_sync(0xffffffffu, mx, off));
    if ((tid & 31) == 0) red[tid >> 5] = mx;
    __syncthreads();
    if (tid < 32) {
        float m = (tid < 8) ? red[tid] : -CUDART_INF_F;
        #pragma unroll
        for (int off = 4; off; off >>= 1) m = fmaxf(m, __shfl_xor_sync(0xffffffffu, m, off));
        red[tid] = m;
    }
    __syncthreads();
    mx = red[0];

    float s = 0.f;
    #pragma unroll
    for (int j = 0; j < 8; j++) { float ev = __expf(vals[j] - mx); vals[j] = ev; s += ev; }
    #pragma unroll
    for (int off = 16; off; off >>= 1) s += __shfl_xor_sync(0xffffffffu, s, off);
    __syncthreads();
    if ((tid & 31) == 0) red[tid >> 5] = s;
    __syncthreads();
    if (tid < 32) {
        float m = (tid < 8) ? red[tid] : 0.f;
        #pragma unroll
        for (int off = 4; off; off >>= 1) m += __shfl_xor_sync(0xffffffffu, m, off);
        red[tid] = m;
    }
    __syncthreads();
    float inv = 1.f / red[0];
    #pragma unroll
    for (int j = 0; j < 8; j++) out_w[(size_t)b * TT + tid + j * 256] = vals[j] * inv;
}

// ---------------- K3: context partials (MLP=16 batched loads) ----------------
__global__ __launch_bounds__(128) void context_kernel(
    const float* __restrict__ memory, const float* __restrict__ wgt)
{
    __shared__ float s_w[128];
    int tid = threadIdx.x;
    int b = blockIdx.y, ts = blockIdx.x;
    int t0 = ts * 128;
    s_w[tid] = wgt[(size_t)b * TT + t0 + tid];
    __syncthreads();

    const float4* m4 = (const float4*)(memory + ((size_t)b * TT + t0) * DEMB) + tid;
    float4 acc = make_float4(0.f, 0.f, 0.f, 0.f);
    for (int i = 0; i < 128; i += 16) {
        float4 v[16];
        #pragma unroll
        for (int u = 0; u < 16; u++) v[u] = m4[(size_t)(i + u) * 128];
        #pragma unroll
        for (int u = 0; u < 16; u++) {
            float w = s_w[i + u];
            acc.x = fmaf(w, v[u].x, acc.x);
            acc.y = fmaf(w, v[u].y, acc.y);
            acc.z = fmaf(w, v[u].z, acc.z);
            acc.w = fmaf(w, v[u].w, acc.w);
        }
    }
    ((float4*)g_ctx_part)[(size_t)ts * (BB * DEMB / 4) + b * (DEMB / 4) + tid] = acc;
}

// ---------------- K4: reduce context partials ----------------
__global__ __launch_bounds__(256) void reduce_kernel(float* __restrict__ out_ctx)
{
    int i = blockIdx.x * 256 + threadIdx.x;
    float s = 0.f;
    #pragma unroll
    for (int ts = 0; ts < NSPLIT; ts++) s += g_ctx_part[(size_t)ts * BB * DEMB + i];
    out_ctx[i] = s;
}

// ---------------- launch ----------------
extern "C" void kernel_launch(void* const* d_in, const int* in_sizes, int n_in,
                              void* d_out, int out_size)
{
    const float* hidden = (const float*)d_in[0];
    const float* memory = (const float*)d_in[1];
    const float* pm     = (const float*)d_in[2];
    const float* awc    = (const float*)d_in[3];
    const int*   mask   = (const int*)d_in[4];
    const float* Wq     = (const float*)d_in[5];
    const float* Wv     = (const float*)d_in[6];
    const float* convw  = (const float*)d_in[7];
    const float* Wd     = (const float*)d_in[8];

    float* out     = (float*)d_out;
    float* out_ctx = out;                  // [B, 512]
    float* out_w   = out + BB * DEMB;      // [B, T]

    cudaFuncSetAttribute(energy_kernel,
                         cudaFuncAttributeMaxDynamicSharedMemorySize, SM_TOTAL);

    prep_kernel<<<dim3(64, 16), 128>>>(hidden, Wq, convw, Wd);
    dummy_kernel<<<1, 32>>>();
    dummy_kernel<<<1, 32>>>();
    energy_kernel<<<dim3(16, 64), 256, SM_TOTAL>>>(pm, awc, Wv);
    softmax_kernel<<<64, 256>>>(mask, out_w);
    context_kernel<<<dim3(NSPLIT, 64), 128>>>(memory, out_w);
    reduce_kernel<<<128, 256>>>(out_ctx);
}

// round 13
// speedup vs baseline: 1.0407x; 1.0407x over previous
#include <cuda_runtime.h>
#include <cuda_bf16.h>
#include <math_constants.h>
#include <cstdint>

#define BB    64
#define TT    2048
#define DRNN  1024
#define DEMB  512
#define DATT  128
#define NF    32
#define KS    31
#define PADW  15
#define NSPLIT 32

#define KPAD   104
#define ROWB   208

// ---- energy kernel dynamic smem layout (bytes) ----
#define SM_B     0                         // Wd image: 128 x 208 B
#define SM_LOCB  26624                     // loc bf16: 128 x 208 B
#define SM_AW    53248                     // 2*160 floats
#define SM_CW    54528                     // 62*32 floats
#define SM_PQ    62464                     // 128 floats
#define SM_WV    62976                     // 128 floats
#define SM_E     63488                     // 128 floats
#define SM_TOTAL 64000

// ---------------- device scratch ----------------
__device__ float  g_pq[BB * DATT];
__device__ float2 g_cw2[62 * 16];
__device__ unsigned short g_wdbp[128 * KPAD];  // B image [a][k] bf16: Wh|Wh|Wl|0pad
__device__ float  g_energy[BB * TT];
__device__ float  g_ctx_part[NSPLIT * BB * DEMB];

typedef unsigned long long ull;

// ---------------- helpers ----------------
__device__ __forceinline__ ull ffma2u(ull a, ull b, ull c) {
    ull d;
    asm("fma.rn.f32x2 %0, %1, %2, %3;" : "=l"(d) : "l"(a), "l"(b), "l"(c));
    return d;
}
__device__ __forceinline__ ull pack2(float x, float y) {
    ull r; asm("mov.b64 %0, {%1, %2};" : "=l"(r) : "f"(x), "f"(y)); return r;
}
__device__ __forceinline__ float2 unpack2(ull v) {
    float2 f; asm("mov.b64 {%0, %1}, %2;" : "=f"(f.x), "=f"(f.y) : "l"(v)); return f;
}
__device__ __forceinline__ float tanh_fast(float x) {
    float y; asm("tanh.approx.f32 %0, %1;" : "=f"(y) : "f"(x)); return y;
}
__device__ __forceinline__ uint32_t smem_u32(const void* p) {
    uint32_t a;
    asm("{ .reg .u64 t; cvta.to.shared.u64 t, %1; cvt.u32.u64 %0, t; }" : "=r"(a) : "l"(p));
    return a;
}
__device__ __forceinline__ void ldsm4(uint32_t* r, uint32_t addr) {
    asm volatile("ldmatrix.sync.aligned.m8n8.x4.shared.b16 {%0,%1,%2,%3}, [%4];"
        : "=r"(r[0]), "=r"(r[1]), "=r"(r[2]), "=r"(r[3]) : "r"(addr));
}
__device__ __forceinline__ void mma_bf16(float* d, const uint32_t* a,
                                         uint32_t b0, uint32_t b1) {
    asm volatile("mma.sync.aligned.m16n8k16.row.col.f32.bf16.bf16.f32 "
        "{%0,%1,%2,%3}, {%4,%5,%6,%7}, {%8,%9}, {%0,%1,%2,%3};"
        : "+f"(d[0]), "+f"(d[1]), "+f"(d[2]), "+f"(d[3])
        : "r"(a[0]), "r"(a[1]), "r"(a[2]), "r"(a[3]), "r"(b0), "r"(b1));
}

// ---------------- K0: pq GEMM (16x parallel) + conv repack + Wd bf16 image ----------------
__global__ __launch_bounds__(128) void prep_kernel(
    const float* __restrict__ hidden, const float* __restrict__ Wq,
    const float* __restrict__ convw,  const float* __restrict__ Wd)
{
    __shared__ float s_h[DRNN];
    int tid = threadIdx.x, b = blockIdx.x, slice = blockIdx.y;
    for (int i = tid; i < DRNN; i += 128) s_h[i] = hidden[(size_t)b * DRNN + i];
    __syncthreads();

    int w = tid >> 5, lane = tid & 31;
    int a0 = slice * 8 + w * 2;
    const float* wq0 = Wq + (size_t)a0 * DRNN;
    const float* wq1 = wq0 + DRNN;
    float a00 = 0.f, a01 = 0.f, a10 = 0.f, a11 = 0.f;
    #pragma unroll 4
    for (int k = lane; k < DRNN; k += 64) {
        float h0 = s_h[k], h1 = s_h[k + 32];
        a00 = fmaf(h0, wq0[k],      a00);
        a01 = fmaf(h1, wq0[k + 32], a01);
        a10 = fmaf(h0, wq1[k],      a10);
        a11 = fmaf(h1, wq1[k + 32], a11);
    }
    float rA = a00 + a01, rB = a10 + a11;
    #pragma unroll
    for (int off = 16; off; off >>= 1) {
        rA += __shfl_down_sync(0xffffffffu, rA, off);
        rB += __shfl_down_sync(0xffffffffu, rB, off);
    }
    if (lane == 0) {
        g_pq[b * DATT + a0]     = rA;
        g_pq[b * DATT + a0 + 1] = rB;
    }

    if (b == 0 && slice == 0) {
        for (int i = tid; i < 62 * 16; i += 128) {
            int ck = i >> 4, fp = i & 15;
            g_cw2[i] = make_float2(convw[(2 * fp) * 62 + ck], convw[(2 * fp + 1) * 62 + ck]);
        }
    }
    if (b == 1 && slice == 0) {
        int a = tid;
        if (a < 128) {
            const float* wrow = Wd + a * NF;
            unsigned short* orow = g_wdbp + a * KPAD;
            #pragma unroll 4
            for (int k = 0; k < KPAD; k++) {
                __nv_bfloat16 bv = __float2bfloat16(0.f);
                if (k < 64) {
                    bv = __float2bfloat16(wrow[k & 31]);
                } else if (k < 96) {
                    float orig = wrow[k - 64];
                    float hi = __bfloat162float(__float2bfloat16(orig));
                    bv = __float2bfloat16(orig - hi);
                }
                orow[k] = *(unsigned short*)&bv;
            }
        }
    }
}

// ---------------- K1: conv + mma.sync paw + tanh + v-dot -> energies ----------------
// R11 version (measured 44.8 us): 256 threads = 8 warps, warp owns m16 tile.
__global__ __launch_bounds__(256) void energy_kernel(
    const float* __restrict__ pm, const float* __restrict__ aw,
    const float* __restrict__ wv)
{
    extern __shared__ __align__(16) char smc[];
    float* s_aw = (float*)(smc + SM_AW);
    float* s_cw = (float*)(smc + SM_CW);
    float* s_pq = (float*)(smc + SM_PQ);
    float* s_wv = (float*)(smc + SM_WV);
    float* s_e  = (float*)(smc + SM_E);

    int tid = threadIdx.x;
    int b   = blockIdx.y;
    int t0  = blockIdx.x * 128;
    int w   = tid >> 5, lane = tid & 31;
    uint32_t sbase = smem_u32(smc);

    // ---- stage: B image, conv inputs, pq, wv ----
    {
        const float4* src = (const float4*)g_wdbp;     // 1664 float4
        float4* dst = (float4*)(smc + SM_B);
        for (int i = tid; i < 1664; i += 256) dst[i] = src[i];
    }
    const float* awB = aw + (size_t)b * 2 * TT;
    for (int i = tid; i < 2 * 158; i += 256) {
        int c = i / 158, j = i - c * 158;
        int tg = t0 + j - PADW;
        s_aw[c * 160 + j] = (tg >= 0 && tg < TT) ? awB[(size_t)c * TT + tg] : 0.f;
    }
    {
        const float4* src = (const float4*)g_cw2;      // 496 float4
        float4* dst = (float4*)s_cw;
        for (int i = tid; i < 496; i += 256) dst[i] = src[i];
    }
    if (tid < 128) {
        s_pq[tid] = g_pq[b * DATT + tid];
        s_wv[tid] = wv[tid];
    }
    __syncthreads();

    // ---- conv: thread (tloc = tid&127, fh = tid>>7) -> loc[t][16 filters] ----
    {
        const int tloc = tid & 127, fh = tid >> 7;
        ull cacc[8];
        #pragma unroll
        for (int i = 0; i < 8; i++) cacc[i] = 0ULL;
        #pragma unroll 2
        for (int ck = 0; ck < 62; ck++) {
            int c = (ck >= 31), k = ck - c * 31;
            float av = s_aw[c * 160 + tloc + k];
            ull av2 = pack2(av, av);
            const ulonglong2* row = (const ulonglong2*)(s_cw + ck * 32 + fh * 16);
            #pragma unroll
            for (int q = 0; q < 4; q++) {
                ulonglong2 w2 = row[q];
                cacc[2 * q]     = ffma2u(av2, w2.x, cacc[2 * q]);
                cacc[2 * q + 1] = ffma2u(av2, w2.y, cacc[2 * q + 1]);
            }
        }
        uint32_t awords[24];
        #pragma unroll
        for (int fp = 0; fp < 8; fp++) {
            float2 v = unpack2(cacc[fp]);
            __nv_bfloat16 h0 = __float2bfloat16(v.x), h1 = __float2bfloat16(v.y);
            float r0 = v.x - __bfloat162float(h0);
            float r1 = v.y - __bfloat162float(h1);
            __nv_bfloat16 l0 = __float2bfloat16(r0), l1 = __float2bfloat16(r1);
            uint32_t hw = ((uint32_t)__bfloat16_as_ushort(h1) << 16) | __bfloat16_as_ushort(h0);
            uint32_t lw = ((uint32_t)__bfloat16_as_ushort(l1) << 16) | __bfloat16_as_ushort(l0);
            awords[fp]      = hw;
            awords[8 + fp]  = lw;
            awords[16 + fp] = hw;
        }
        char* base = smc + SM_LOCB + tloc * ROWB + fh * 32;
        #pragma unroll
        for (int sgm = 0; sgm < 3; sgm++) {
            uint4* dst = (uint4*)(base + sgm * 64);
            dst[0] = make_uint4(awords[8 * sgm],     awords[8 * sgm + 1],
                                awords[8 * sgm + 2], awords[8 * sgm + 3]);
            dst[1] = make_uint4(awords[8 * sgm + 4], awords[8 * sgm + 5],
                                awords[8 * sgm + 6], awords[8 * sgm + 7]);
        }
    }
    __syncthreads();

    // ---- per-warp MMA + epilogue (m16 tile rows mb..mb+15) ----
    const int mb = w * 16;
    const uint32_t sLocb = sbase + SM_LOCB;
    const uint32_t sBimg = sbase + SM_B;
    const int r0 = mb + (lane >> 2);
    const float* pr0 = pm + ((size_t)b * TT + t0 + r0) * DATT;
    const float* pr1 = pr0 + 8 * DATT;
    const int ac = 2 * (lane & 3);

    float es0 = 0.f, es1 = 0.f;

    #pragma unroll
    for (int nh = 0; nh < 2; nh++) {
        // prefetch pm fragments for this n-half (independent of MMA -> hides DRAM)
        float2 pv0[8], pv1[8];
        #pragma unroll
        for (int nt = 0; nt < 8; nt++) {
            int a0 = nh * 64 + nt * 8 + ac;
            pv0[nt] = *(const float2*)(pr0 + a0);
            pv1[nt] = *(const float2*)(pr1 + a0);
        }

        float acc[8][4];
        #pragma unroll
        for (int nt = 0; nt < 8; nt++)
            #pragma unroll
            for (int q = 0; q < 4; q++) acc[nt][q] = 0.f;

        #pragma unroll
        for (int ks = 0; ks < 6; ks++) {
            const int kk = ks * 16;
            uint32_t af[4];
            ldsm4(af, sLocb + (mb + (lane & 15)) * ROWB + (kk + (lane >> 4) * 8) * 2);
            uint32_t bf[4][4];
            #pragma unroll
            for (int ng = 0; ng < 4; ng++) {
                uint32_t baddr = sBimg
                    + (nh * 64 + ng * 16 + ((lane >> 4) << 3) + (lane & 7)) * ROWB
                    + (kk + ((lane >> 3) & 1) * 8) * 2;
                ldsm4(bf[ng], baddr);
            }
            #pragma unroll
            for (int ng = 0; ng < 4; ng++) {
                mma_bf16(acc[2 * ng],     af, bf[ng][0], bf[ng][1]);
                mma_bf16(acc[2 * ng + 1], af, bf[ng][2], bf[ng][3]);
            }
        }

        #pragma unroll
        for (int nt = 0; nt < 8; nt++) {
            int a0 = nh * 64 + nt * 8 + ac;
            float2 q = *(const float2*)(s_pq + a0);
            float2 v = *(const float2*)(s_wv + a0);
            const float* c = acc[nt];
            es0 = fmaf(v.x, tanh_fast(c[0] + q.x + pv0[nt].x), es0);
            es0 = fmaf(v.y, tanh_fast(c[1] + q.y + pv0[nt].y), es0);
            es1 = fmaf(v.x, tanh_fast(c[2] + q.x + pv1[nt].x), es1);
            es1 = fmaf(v.y, tanh_fast(c[3] + q.y + pv1[nt].y), es1);
        }
    }

    // quad reduction (lanes l^1, l^2)
    #pragma unroll
    for (int off = 1; off <= 2; off <<= 1) {
        es0 += __shfl_xor_sync(0xffffffffu, es0, off);
        es1 += __shfl_xor_sync(0xffffffffu, es1, off);
    }
    if ((lane & 3) == 0) {
        s_e[r0]     = es0;
        s_e[r0 + 8] = es1;
    }
    __syncthreads();
    if (tid < 128) g_energy[(size_t)b * TT + t0 + tid] = s_e[tid];
}

// ---------------- K2: masked softmax (mask = int32) ----------------
__global__ __launch_bounds__(256) void softmax_kernel(
    const int* __restrict__ mask, float* __restrict__ out_w)
{
    __shared__ float red[32];
    int tid = threadIdx.x, b = blockIdx.x;
    float vals[8];
    float mx = -CUDART_INF_F;
    #pragma unroll
    for (int j = 0; j < 8; j++) {
        int t = tid + j * 256;
        float e = g_energy[(size_t)b * TT + t];
        float v = (mask[(size_t)b * TT + t] != 0) ? -CUDART_INF_F : e;
        vals[j] = v;
        mx = fmaxf(mx, v);
    }
    #pragma unroll
    for (int off = 16; off; off >>= 1) mx = fmaxf(mx, __shfl_xor_sync(0xffffffffu, mx, off));
    if ((tid & 31) == 0) red[tid >> 5] = mx;
    __syncthreads();
    if (tid < 32) {
        float m = (tid < 8) ? red[tid] : -CUDART_INF_F;
        #pragma unroll
        for (int off = 4; off; off >>= 1) m = fmaxf(m, __shfl_xor_sync(0xffffffffu, m, off));
        red[tid] = m;
    }
    __syncthreads();
    mx = red[0];

    float s = 0.f;
    #pragma unroll
    for (int j = 0; j < 8; j++) { float ev = __expf(vals[j] - mx); vals[j] = ev; s += ev; }
    #pragma unroll
    for (int off = 16; off; off >>= 1) s += __shfl_xor_sync(0xffffffffu, s, off);
    __syncthreads();
    if ((tid & 31) == 0) red[tid >> 5] = s;
    __syncthreads();
    if (tid < 32) {
        float m = (tid < 8) ? red[tid] : 0.f;
        #pragma unroll
        for (int off = 4; off; off >>= 1) m += __shfl_xor_sync(0xffffffffu, m, off);
        red[tid] = m;
    }
    __syncthreads();
    float inv = 1.f / red[0];
    #pragma unroll
    for (int j = 0; j < 8; j++) out_w[(size_t)b * TT + tid + j * 256] = vals[j] * inv;
}

// ---------------- K3: context partials (R3-measured shape: 64 t, MLP=8) ----------------
__global__ __launch_bounds__(128) void context_kernel(
    const float* __restrict__ memory, const float* __restrict__ wgt)
{
    __shared__ float s_w[64];
    int tid = threadIdx.x;
    int b = blockIdx.y, ts = blockIdx.x;
    int t0 = ts * 64;
    if (tid < 64) s_w[tid] = wgt[(size_t)b * TT + t0 + tid];
    __syncthreads();

    const float4* m4 = (const float4*)(memory + ((size_t)b * TT + t0) * DEMB) + tid;
    float4 acc = make_float4(0.f, 0.f, 0.f, 0.f);
    for (int i = 0; i < 64; i += 8) {
        float4 v[8];
        #pragma unroll
        for (int u = 0; u < 8; u++) v[u] = m4[(size_t)(i + u) * 128];
        #pragma unroll
        for (int u = 0; u < 8; u++) {
            float w = s_w[i + u];
            acc.x = fmaf(w, v[u].x, acc.x);
            acc.y = fmaf(w, v[u].y, acc.y);
            acc.z = fmaf(w, v[u].z, acc.z);
            acc.w = fmaf(w, v[u].w, acc.w);
        }
    }
    ((float4*)g_ctx_part)[(size_t)ts * (BB * DEMB / 4) + b * (DEMB / 4) + tid] = acc;
}

// ---------------- K4: reduce context partials ----------------
__global__ __launch_bounds__(256) void reduce_kernel(float* __restrict__ out_ctx)
{
    int i = blockIdx.x * 256 + threadIdx.x;
    float s = 0.f;
    #pragma unroll
    for (int ts = 0; ts < NSPLIT; ts++) s += g_ctx_part[(size_t)ts * BB * DEMB + i];
    out_ctx[i] = s;
}

// ---------------- launch ----------------
// NOTE: no dummy kernels this round — the ncu capture slot (4th launch)
// lands on context_kernel so we finally measure it.
extern "C" void kernel_launch(void* const* d_in, const int* in_sizes, int n_in,
                              void* d_out, int out_size)
{
    const float* hidden = (const float*)d_in[0];
    const float* memory = (const float*)d_in[1];
    const float* pm     = (const float*)d_in[2];
    const float* awc    = (const float*)d_in[3];
    const int*   mask   = (const int*)d_in[4];
    const float* Wq     = (const float*)d_in[5];
    const float* Wv     = (const float*)d_in[6];
    const float* convw  = (const float*)d_in[7];
    const float* Wd     = (const float*)d_in[8];

    float* out     = (float*)d_out;
    float* out_ctx = out;                  // [B, 512]
    float* out_w   = out + BB * DEMB;      // [B, T]

    cudaFuncSetAttribute(energy_kernel,
                         cudaFuncAttributeMaxDynamicSharedMemorySize, SM_TOTAL);

    prep_kernel<<<dim3(64, 16), 128>>>(hidden, Wq, convw, Wd);
    energy_kernel<<<dim3(16, 64), 256, SM_TOTAL>>>(pm, awc, Wv);
    softmax_kernel<<<64, 256>>>(mask, out_w);
    context_kernel<<<dim3(NSPLIT, 64), 128>>>(memory, out_w);
    reduce_kernel<<<128, 256>>>(out_ctx);
}

// round 14
// speedup vs baseline: 1.0660x; 1.0243x over previous
#include <cuda_runtime.h>
#include <cuda_bf16.h>
#include <math_constants.h>
#include <cstdint>

#define BB    64
#define TT    2048
#define DRNN  1024
#define DEMB  512
#define DATT  128
#define NF    32
#define KS    31
#define PADW  15
#define NSPLIT 32

#define KPAD   104
#define ROWB   208

// ---- energy kernel dynamic smem layout (bytes) ----
#define SM_B     0                         // Wd image: 128 x 208 B
#define SM_LOCB  26624                     // loc bf16: 128 x 208 B
#define SM_AW    53248                     // 2*160 floats
#define SM_CW    54528                     // 62*32 floats
#define SM_PQ    62464                     // 128 floats
#define SM_WV    62976                     // 128 floats
#define SM_E     63488                     // 128 floats
#define SM_TOTAL 64000

// ---------------- device scratch ----------------
__device__ float  g_pq[BB * DATT];
__device__ float2 g_cw2[62 * 16];
__device__ unsigned short g_wdbp[128 * KPAD];  // B image [a][k] bf16: Wh|Wh|Wl|0pad
__device__ float  g_wun[BB * TT];              // unnormalized softmax weights
__device__ float  g_esum[BB * 16];             // per-(b, t-block) partial exp sums
__device__ float  g_ctx_part[NSPLIT * BB * DEMB];

typedef unsigned long long ull;

// ---------------- helpers ----------------
__device__ __forceinline__ ull ffma2u(ull a, ull b, ull c) {
    ull d;
    asm("fma.rn.f32x2 %0, %1, %2, %3;" : "=l"(d) : "l"(a), "l"(b), "l"(c));
    return d;
}
__device__ __forceinline__ ull pack2(float x, float y) {
    ull r; asm("mov.b64 %0, {%1, %2};" : "=l"(r) : "f"(x), "f"(y)); return r;
}
__device__ __forceinline__ float2 unpack2(ull v) {
    float2 f; asm("mov.b64 {%0, %1}, %2;" : "=f"(f.x), "=f"(f.y) : "l"(v)); return f;
}
__device__ __forceinline__ float tanh_fast(float x) {
    float y; asm("tanh.approx.f32 %0, %1;" : "=f"(y) : "f"(x)); return y;
}
__device__ __forceinline__ uint32_t smem_u32(const void* p) {
    uint32_t a;
    asm("{ .reg .u64 t; cvta.to.shared.u64 t, %1; cvt.u32.u64 %0, t; }" : "=r"(a) : "l"(p));
    return a;
}
__device__ __forceinline__ void ldsm4(uint32_t* r, uint32_t addr) {
    asm volatile("ldmatrix.sync.aligned.m8n8.x4.shared.b16 {%0,%1,%2,%3}, [%4];"
        : "=r"(r[0]), "=r"(r[1]), "=r"(r[2]), "=r"(r[3]) : "r"(addr));
}
__device__ __forceinline__ void mma_bf16(float* d, const uint32_t* a,
                                         uint32_t b0, uint32_t b1) {
    asm volatile("mma.sync.aligned.m16n8k16.row.col.f32.bf16.bf16.f32 "
        "{%0,%1,%2,%3}, {%4,%5,%6,%7}, {%8,%9}, {%0,%1,%2,%3};"
        : "+f"(d[0]), "+f"(d[1]), "+f"(d[2]), "+f"(d[3])
        : "r"(a[0]), "r"(a[1]), "r"(a[2]), "r"(a[3]), "r"(b0), "r"(b1));
}

// ---------------- K0: pq GEMM (16x parallel) + conv repack + Wd bf16 image ----------------
__global__ __launch_bounds__(128) void prep_kernel(
    const float* __restrict__ hidden, const float* __restrict__ Wq,
    const float* __restrict__ convw,  const float* __restrict__ Wd)
{
    __shared__ float s_h[DRNN];
    int tid = threadIdx.x, b = blockIdx.x, slice = blockIdx.y;
    for (int i = tid; i < DRNN; i += 128) s_h[i] = hidden[(size_t)b * DRNN + i];
    __syncthreads();

    int w = tid >> 5, lane = tid & 31;
    int a0 = slice * 8 + w * 2;
    const float* wq0 = Wq + (size_t)a0 * DRNN;
    const float* wq1 = wq0 + DRNN;
    float a00 = 0.f, a01 = 0.f, a10 = 0.f, a11 = 0.f;
    #pragma unroll 4
    for (int k = lane; k < DRNN; k += 64) {
        float h0 = s_h[k], h1 = s_h[k + 32];
        a00 = fmaf(h0, wq0[k],      a00);
        a01 = fmaf(h1, wq0[k + 32], a01);
        a10 = fmaf(h0, wq1[k],      a10);
        a11 = fmaf(h1, wq1[k + 32], a11);
    }
    float rA = a00 + a01, rB = a10 + a11;
    #pragma unroll
    for (int off = 16; off; off >>= 1) {
        rA += __shfl_down_sync(0xffffffffu, rA, off);
        rB += __shfl_down_sync(0xffffffffu, rB, off);
    }
    if (lane == 0) {
        g_pq[b * DATT + a0]     = rA;
        g_pq[b * DATT + a0 + 1] = rB;
    }

    if (b == 0 && slice == 0) {
        for (int i = tid; i < 62 * 16; i += 128) {
            int ck = i >> 4, fp = i & 15;
            g_cw2[i] = make_float2(convw[(2 * fp) * 62 + ck], convw[(2 * fp + 1) * 62 + ck]);
        }
    }
    if (b == 1 && slice == 0) {
        int a = tid;
        if (a < 128) {
            const float* wrow = Wd + a * NF;
            unsigned short* orow = g_wdbp + a * KPAD;
            #pragma unroll 4
            for (int k = 0; k < KPAD; k++) {
                __nv_bfloat16 bv = __float2bfloat16(0.f);
                if (k < 64) {
                    bv = __float2bfloat16(wrow[k & 31]);
                } else if (k < 96) {
                    float orig = wrow[k - 64];
                    float hi = __bfloat162float(__float2bfloat16(orig));
                    bv = __float2bfloat16(orig - hi);
                }
                orow[k] = *(unsigned short*)&bv;
            }
        }
    }
}

// ---------------- K1: conv + mma.sync paw + tanh + v-dot + mask/exp -> unnorm weights ----------------
// R11 energy core; epilogue now applies mask + expf and emits per-block sum
// (softmax kernel eliminated: energies are bounded by sum|wv| so skip-max exp is safe).
__global__ __launch_bounds__(256) void energy_kernel(
    const float* __restrict__ pm, const float* __restrict__ aw,
    const float* __restrict__ wv, const int* __restrict__ mask)
{
    extern __shared__ __align__(16) char smc[];
    float* s_aw = (float*)(smc + SM_AW);
    float* s_cw = (float*)(smc + SM_CW);
    float* s_pq = (float*)(smc + SM_PQ);
    float* s_wv = (float*)(smc + SM_WV);
    float* s_e  = (float*)(smc + SM_E);

    int tid = threadIdx.x;
    int b   = blockIdx.y;
    int t0  = blockIdx.x * 128;
    int w   = tid >> 5, lane = tid & 31;
    uint32_t sbase = smem_u32(smc);

    // ---- stage: B image, conv inputs, pq, wv ----
    {
        const float4* src = (const float4*)g_wdbp;     // 1664 float4
        float4* dst = (float4*)(smc + SM_B);
        for (int i = tid; i < 1664; i += 256) dst[i] = src[i];
    }
    const float* awB = aw + (size_t)b * 2 * TT;
    for (int i = tid; i < 2 * 158; i += 256) {
        int c = i / 158, j = i - c * 158;
        int tg = t0 + j - PADW;
        s_aw[c * 160 + j] = (tg >= 0 && tg < TT) ? awB[(size_t)c * TT + tg] : 0.f;
    }
    {
        const float4* src = (const float4*)g_cw2;      // 496 float4
        float4* dst = (float4*)s_cw;
        for (int i = tid; i < 496; i += 256) dst[i] = src[i];
    }
    if (tid < 128) {
        s_pq[tid] = g_pq[b * DATT + tid];
        s_wv[tid] = wv[tid];
    }
    __syncthreads();

    // ---- conv: thread (tloc = tid&127, fh = tid>>7) -> loc[t][16 filters] ----
    {
        const int tloc = tid & 127, fh = tid >> 7;
        ull cacc[8];
        #pragma unroll
        for (int i = 0; i < 8; i++) cacc[i] = 0ULL;
        #pragma unroll 2
        for (int ck = 0; ck < 62; ck++) {
            int c = (ck >= 31), k = ck - c * 31;
            float av = s_aw[c * 160 + tloc + k];
            ull av2 = pack2(av, av);
            const ulonglong2* row = (const ulonglong2*)(s_cw + ck * 32 + fh * 16);
            #pragma unroll
            for (int q = 0; q < 4; q++) {
                ulonglong2 w2 = row[q];
                cacc[2 * q]     = ffma2u(av2, w2.x, cacc[2 * q]);
                cacc[2 * q + 1] = ffma2u(av2, w2.y, cacc[2 * q + 1]);
            }
        }
        uint32_t awords[24];
        #pragma unroll
        for (int fp = 0; fp < 8; fp++) {
            float2 v = unpack2(cacc[fp]);
            __nv_bfloat16 h0 = __float2bfloat16(v.x), h1 = __float2bfloat16(v.y);
            float r0 = v.x - __bfloat162float(h0);
            float r1 = v.y - __bfloat162float(h1);
            __nv_bfloat16 l0 = __float2bfloat16(r0), l1 = __float2bfloat16(r1);
            uint32_t hw = ((uint32_t)__bfloat16_as_ushort(h1) << 16) | __bfloat16_as_ushort(h0);
            uint32_t lw = ((uint32_t)__bfloat16_as_ushort(l1) << 16) | __bfloat16_as_ushort(l0);
            awords[fp]      = hw;
            awords[8 + fp]  = lw;
            awords[16 + fp] = hw;
        }
        char* base = smc + SM_LOCB + tloc * ROWB + fh * 32;
        #pragma unroll
        for (int sgm = 0; sgm < 3; sgm++) {
            uint4* dst = (uint4*)(base + sgm * 64);
            dst[0] = make_uint4(awords[8 * sgm],     awords[8 * sgm + 1],
                                awords[8 * sgm + 2], awords[8 * sgm + 3]);
            dst[1] = make_uint4(awords[8 * sgm + 4], awords[8 * sgm + 5],
                                awords[8 * sgm + 6], awords[8 * sgm + 7]);
        }
    }
    __syncthreads();

    // ---- per-warp MMA + epilogue (m16 tile rows mb..mb+15) ----
    const int mb = w * 16;
    const uint32_t sLocb = sbase + SM_LOCB;
    const uint32_t sBimg = sbase + SM_B;
    const int r0 = mb + (lane >> 2);
    const float* pr0 = pm + ((size_t)b * TT + t0 + r0) * DATT;
    const float* pr1 = pr0 + 8 * DATT;
    const int ac = 2 * (lane & 3);

    float es0 = 0.f, es1 = 0.f;

    #pragma unroll
    for (int nh = 0; nh < 2; nh++) {
        float2 pv0[8], pv1[8];
        #pragma unroll
        for (int nt = 0; nt < 8; nt++) {
            int a0 = nh * 64 + nt * 8 + ac;
            pv0[nt] = *(const float2*)(pr0 + a0);
            pv1[nt] = *(const float2*)(pr1 + a0);
        }

        float acc[8][4];
        #pragma unroll
        for (int nt = 0; nt < 8; nt++)
            #pragma unroll
            for (int q = 0; q < 4; q++) acc[nt][q] = 0.f;

        #pragma unroll
        for (int ks = 0; ks < 6; ks++) {
            const int kk = ks * 16;
            uint32_t af[4];
            ldsm4(af, sLocb + (mb + (lane & 15)) * ROWB + (kk + (lane >> 4) * 8) * 2);
            uint32_t bf[4][4];
            #pragma unroll
            for (int ng = 0; ng < 4; ng++) {
                uint32_t baddr = sBimg
                    + (nh * 64 + ng * 16 + ((lane >> 4) << 3) + (lane & 7)) * ROWB
                    + (kk + ((lane >> 3) & 1) * 8) * 2;
                ldsm4(bf[ng], baddr);
            }
            #pragma unroll
            for (int ng = 0; ng < 4; ng++) {
                mma_bf16(acc[2 * ng],     af, bf[ng][0], bf[ng][1]);
                mma_bf16(acc[2 * ng + 1], af, bf[ng][2], bf[ng][3]);
            }
        }

        #pragma unroll
        for (int nt = 0; nt < 8; nt++) {
            int a0 = nh * 64 + nt * 8 + ac;
            float2 q = *(const float2*)(s_pq + a0);
            float2 v = *(const float2*)(s_wv + a0);
            const float* c = acc[nt];
            es0 = fmaf(v.x, tanh_fast(c[0] + q.x + pv0[nt].x), es0);
            es0 = fmaf(v.y, tanh_fast(c[1] + q.y + pv0[nt].y), es0);
            es1 = fmaf(v.x, tanh_fast(c[2] + q.x + pv1[nt].x), es1);
            es1 = fmaf(v.y, tanh_fast(c[3] + q.y + pv1[nt].y), es1);
        }
    }

    #pragma unroll
    for (int off = 1; off <= 2; off <<= 1) {
        es0 += __shfl_xor_sync(0xffffffffu, es0, off);
        es1 += __shfl_xor_sync(0xffffffffu, es1, off);
    }
    if ((lane & 3) == 0) {
        s_e[r0]     = es0;
        s_e[r0 + 8] = es1;
    }
    __syncthreads();

    // ---- mask + exp -> unnormalized weights; block partial sum ----
    if (tid < 128) {
        float e = s_e[tid];
        float wu = (mask[(size_t)b * TT + t0 + tid] != 0) ? 0.f : __expf(e);
        g_wun[(size_t)b * TT + t0 + tid] = wu;
        s_e[tid] = wu;
    }
    __syncthreads();
    if (tid < 32) {
        float s = s_e[tid] + s_e[tid + 32] + s_e[tid + 64] + s_e[tid + 96];
        #pragma unroll
        for (int off = 16; off; off >>= 1) s += __shfl_down_sync(0xffffffffu, s, off);
        if (tid == 0) g_esum[b * 16 + blockIdx.x] = s;
    }
}

// ---------------- K3: context partials + weight normalization + out_w ----------------
// R3-measured shape: 64 t/block, MLP=8. Each block normalizes its weights with
// the redundantly-computed total exp sum (16 partials, deterministic order).
__global__ __launch_bounds__(128) void context_kernel(
    const float* __restrict__ memory, float* __restrict__ out_w)
{
    __shared__ float s_w[64];
    int tid = threadIdx.x;
    int b = blockIdx.y, ts = blockIdx.x;
    int t0 = ts * 64;

    float tot = 0.f;
    #pragma unroll
    for (int i = 0; i < 16; i++) tot += g_esum[b * 16 + i];
    float inv = 1.f / tot;

    if (tid < 64) {
        float wn = g_wun[(size_t)b * TT + t0 + tid] * inv;
        s_w[tid] = wn;
        out_w[(size_t)b * TT + t0 + tid] = wn;
    }
    __syncthreads();

    const float4* m4 = (const float4*)(memory + ((size_t)b * TT + t0) * DEMB) + tid;
    float4 acc = make_float4(0.f, 0.f, 0.f, 0.f);
    for (int i = 0; i < 64; i += 8) {
        float4 v[8];
        #pragma unroll
        for (int u = 0; u < 8; u++) v[u] = m4[(size_t)(i + u) * 128];
        #pragma unroll
        for (int u = 0; u < 8; u++) {
            float w = s_w[i + u];
            acc.x = fmaf(w, v[u].x, acc.x);
            acc.y = fmaf(w, v[u].y, acc.y);
            acc.z = fmaf(w, v[u].z, acc.z);
            acc.w = fmaf(w, v[u].w, acc.w);
        }
    }
    ((float4*)g_ctx_part)[(size_t)ts * (BB * DEMB / 4) + b * (DEMB / 4) + tid] = acc;
}

// ---------------- K4: reduce context partials ----------------
__global__ __launch_bounds__(256) void reduce_kernel(float* __restrict__ out_ctx)
{
    int i = blockIdx.x * 256 + threadIdx.x;
    float s = 0.f;
    #pragma unroll
    for (int ts = 0; ts < NSPLIT; ts++) s += g_ctx_part[(size_t)ts * BB * DEMB + i];
    out_ctx[i] = s;
}

// ---------------- launch (4 kernels) ----------------
extern "C" void kernel_launch(void* const* d_in, const int* in_sizes, int n_in,
                              void* d_out, int out_size)
{
    const float* hidden = (const float*)d_in[0];
    const float* memory = (const float*)d_in[1];
    const float* pm     = (const float*)d_in[2];
    const float* awc    = (const float*)d_in[3];
    const int*   mask   = (const int*)d_in[4];
    const float* Wq     = (const float*)d_in[5];
    const float* Wv     = (const float*)d_in[6];
    const float* convw  = (const float*)d_in[7];
    const float* Wd     = (const float*)d_in[8];

    float* out     = (float*)d_out;
    float* out_ctx = out;                  // [B, 512]
    float* out_w   = out + BB * DEMB;      // [B, T]

    cudaFuncSetAttribute(energy_kernel,
                         cudaFuncAttributeMaxDynamicSharedMemorySize, SM_TOTAL);

    prep_kernel<<<dim3(64, 16), 128>>>(hidden, Wq, convw, Wd);
    energy_kernel<<<dim3(16, 64), 256, SM_TOTAL>>>(pm, awc, Wv, mask);
    context_kernel<<<dim3(NSPLIT, 64), 128>>>(memory, out_w);
    reduce_kernel<<<128, 256>>>(out_ctx);
}